// round 9
// baseline (speedup 1.0000x reference)
#include <cuda_runtime.h>
#include <cuda_bf16.h>
#include <math.h>

// Problem constants
#define TT 1024
#define BB 64
#define DD 512
#define HH 512
#define KK 1024            // D + H
#define GG 2048            // 4*H
#define EPSV 1e-5f
#define MM (TT * BB)       // 65536
#define OUT_HC_OFF (TT * BB * HH)
#define NBLK 128           // persistent blocks (<= 148 SMs)
#define WRT 64             // writer blocks (phase 2)
#define THR 512
#define WST 264            // smem halfword stride (conflict-free)

// Scratch (device globals — no runtime allocation allowed)
__device__ float g_xw[(size_t)MM * GG];                  // 512 MB
__device__ __nv_bfloat16 g_xhi[(size_t)MM * DD];
__device__ __nv_bfloat16 g_xlo[(size_t)MM * DD];
__device__ __nv_bfloat16 g_whi[(size_t)GG * KK];         // W^T [n][k]
__device__ __nv_bfloat16 g_wlo[(size_t)GG * KK];
__device__ __nv_bfloat16 g_hhi[BB * HH];
__device__ __nv_bfloat16 g_hlo[BB * HH];
__device__ float g_c0[BB * HH];
__device__ float g_part[2 * BB * GG];                     // 2 K-halves of gates
__device__ unsigned g_flags[NBLK * 8];                    // barrier flags, 32B apart

__device__ __forceinline__ void split2(float v, __nv_bfloat16& hi, __nv_bfloat16& lo) {
    hi = __float2bfloat16(v);
    lo = __float2bfloat16(v - __bfloat162float(hi));
}

__device__ __forceinline__ void mma_bf16(float* d, const unsigned* a, const unsigned* b) {
    asm volatile(
        "mma.sync.aligned.m16n8k16.row.col.f32.bf16.bf16.f32 "
        "{%0,%1,%2,%3}, {%4,%5,%6,%7}, {%8,%9}, {%0,%1,%2,%3};\n"
        : "+f"(d[0]), "+f"(d[1]), "+f"(d[2]), "+f"(d[3])
        : "r"(a[0]), "r"(a[1]), "r"(a[2]), "r"(a[3]), "r"(b[0]), "r"(b[1]));
}

__device__ __forceinline__ void ldsm_x4(unsigned* r, const void* p) {
    unsigned addr = (unsigned)__cvta_generic_to_shared(p);
    asm volatile("ldmatrix.sync.aligned.m8n8.x4.shared.b16 {%0,%1,%2,%3}, [%4];"
        : "=r"(r[0]), "=r"(r[1]), "=r"(r[2]), "=r"(r[3]) : "r"(addr));
}
__device__ __forceinline__ void ldsm_x2(unsigned* r, const void* p) {
    unsigned addr = (unsigned)__cvta_generic_to_shared(p);
    asm volatile("ldmatrix.sync.aligned.m8n8.x2.shared.b16 {%0,%1}, [%2];"
        : "=r"(r[0]), "=r"(r[1]) : "r"(addr));
}

__device__ __forceinline__ void cp16(void* smem_dst, const void* gsrc) {
    unsigned d = (unsigned)__cvta_generic_to_shared(smem_dst);
    asm volatile("cp.async.cg.shared.global [%0], [%1], 16;" :: "r"(d), "l"(gsrc));
}
__device__ __forceinline__ void cp_commit() {
    asm volatile("cp.async.commit_group;");
}

__device__ __forceinline__ void st_release(unsigned* p, unsigned v) {
    asm volatile("st.release.gpu.u32 [%0], %1;" :: "l"(p), "r"(v) : "memory");
}
__device__ __forceinline__ unsigned ld_acquire(unsigned* p) {
    unsigned v;
    asm volatile("ld.acquire.gpu.u32 %0, [%1];" : "=r"(v) : "l"(p) : "memory");
    return v;
}

// flag barrier pieces (R7-verified protocol)
__device__ __forceinline__ void bar_arrive(int blk, unsigned val) {
    __syncthreads();
    if (threadIdx.x == 0) st_release(&g_flags[blk * 8], val);
}
__device__ __forceinline__ void bar_wait_all(unsigned val) {
    if (threadIdx.x < NBLK) {
        while (ld_acquire(&g_flags[threadIdx.x * 8]) < val) { }
    }
    __syncthreads();
}
__device__ __forceinline__ void bar_wait_writers(unsigned val) {
    if (threadIdx.x < WRT) {
        while (ld_acquire(&g_flags[threadIdx.x * 8]) < val) { }
    }
    __syncthreads();
}

__device__ __forceinline__ float fast_sig(float x) {
    return __fdividef(1.f, 1.f + __expf(-x));
}
__device__ __forceinline__ float fast_tanh(float x) {
    return __fdividef(2.f, 1.f + __expf(-2.f * x)) - 1.f;
}

// ---------------------------------------------------------------------------
__global__ void init_kernel(const float* __restrict__ h0,
                            const float* __restrict__ c0) {
    int i = blockIdx.x * blockDim.x + threadIdx.x;
    if (i < NBLK * 8) g_flags[i] = 0;
    if (i < BB * HH) {
        split2(h0[i], g_hhi[i], g_hlo[i]);
        g_c0[i] = c0[i];
    }
}

__global__ void split_w_kernel(const float* __restrict__ w) {
    int idx = blockIdx.x * blockDim.x + threadIdx.x;
    if (idx < KK * GG) {
        int k = idx / GG;
        int n = idx % GG;
        __nv_bfloat16 hi, lo;
        split2(w[idx], hi, lo);
        g_whi[(size_t)n * KK + k] = hi;
        g_wlo[(size_t)n * KK + k] = lo;
    }
}

__global__ void split_x_kernel(const float* __restrict__ x) {
    size_t idx = (size_t)blockIdx.x * blockDim.x + threadIdx.x;
    if (idx < (size_t)MM * DD) {
        split2(x[idx], g_xhi[idx], g_xlo[idx]);
    }
}

// ---------------------------------------------------------------------------
// XW = X @ Wx + bias via bf16-split HMMA.  M=65536, N=2048, K=512.
// (verified, unchanged)
// ---------------------------------------------------------------------------
__global__ void __launch_bounds__(256, 1) gemm_x_kernel(const float* __restrict__ bias) {
    __shared__ __nv_bfloat16 Ah[128][40], Al[128][40], Bh[128][40], Bl[128][40];

    const int bn = blockIdx.x * 128;
    const int bm = blockIdx.y * 128;
    const int tid = threadIdx.x;
    const int wid = tid >> 5, lane = tid & 31;
    const int wm = wid & 1, wn = wid >> 1;
    const int lr = lane >> 2, lc = lane & 3;

    float acc[4][4][4];
#pragma unroll
    for (int i = 0; i < 4; i++)
#pragma unroll
        for (int j = 0; j < 4; j++)
#pragma unroll
            for (int q = 0; q < 4; q++) acc[i][j][q] = 0.f;

    const int ldr = tid >> 1;
    const int ldc = (tid & 1) * 16;

    for (int k0 = 0; k0 < DD; k0 += 32) {
        const uint4* s;
        s = (const uint4*)&g_xhi[(size_t)(bm + ldr) * DD + k0 + ldc];
        *(uint4*)&Ah[ldr][ldc] = s[0];  *(uint4*)&Ah[ldr][ldc + 8] = s[1];
        s = (const uint4*)&g_xlo[(size_t)(bm + ldr) * DD + k0 + ldc];
        *(uint4*)&Al[ldr][ldc] = s[0];  *(uint4*)&Al[ldr][ldc + 8] = s[1];
        s = (const uint4*)&g_whi[(size_t)(bn + ldr) * KK + k0 + ldc];
        *(uint4*)&Bh[ldr][ldc] = s[0];  *(uint4*)&Bh[ldr][ldc + 8] = s[1];
        s = (const uint4*)&g_wlo[(size_t)(bn + ldr) * KK + k0 + ldc];
        *(uint4*)&Bl[ldr][ldc] = s[0];  *(uint4*)&Bl[ldr][ldc + 8] = s[1];
        __syncthreads();

#pragma unroll
        for (int ks = 0; ks < 32; ks += 16) {
            unsigned ahi[4][4], alo[4][4], bhi[4][2], blo[4][2];
#pragma unroll
            for (int im = 0; im < 4; im++) {
                int r = wm * 64 + im * 16 + lr;
                ahi[im][0] = *(const unsigned*)&Ah[r][ks + lc * 2];
                ahi[im][1] = *(const unsigned*)&Ah[r + 8][ks + lc * 2];
                ahi[im][2] = *(const unsigned*)&Ah[r][ks + 8 + lc * 2];
                ahi[im][3] = *(const unsigned*)&Ah[r + 8][ks + 8 + lc * 2];
                alo[im][0] = *(const unsigned*)&Al[r][ks + lc * 2];
                alo[im][1] = *(const unsigned*)&Al[r + 8][ks + lc * 2];
                alo[im][2] = *(const unsigned*)&Al[r][ks + 8 + lc * 2];
                alo[im][3] = *(const unsigned*)&Al[r + 8][ks + 8 + lc * 2];
            }
#pragma unroll
            for (int in = 0; in < 4; in++) {
                int n = wn * 32 + in * 8 + lr;
                bhi[in][0] = *(const unsigned*)&Bh[n][ks + lc * 2];
                bhi[in][1] = *(const unsigned*)&Bh[n][ks + 8 + lc * 2];
                blo[in][0] = *(const unsigned*)&Bl[n][ks + lc * 2];
                blo[in][1] = *(const unsigned*)&Bl[n][ks + 8 + lc * 2];
            }
#pragma unroll
            for (int im = 0; im < 4; im++)
#pragma unroll
                for (int in = 0; in < 4; in++) {
                    mma_bf16(acc[im][in], ahi[im], bhi[in]);
                    mma_bf16(acc[im][in], alo[im], bhi[in]);
                    mma_bf16(acc[im][in], ahi[im], blo[in]);
                }
        }
        __syncthreads();
    }

#pragma unroll
    for (int im = 0; im < 4; im++)
#pragma unroll
        for (int in = 0; in < 4; in++) {
            int row = bm + wm * 64 + im * 16 + lr;
            int col = bn + wn * 32 + in * 8 + lc * 2;
            float b0 = bias[col], b1 = bias[col + 1];
            float2 v;
            v.x = acc[im][in][0] + b0; v.y = acc[im][in][1] + b1;
            *(float2*)&g_xw[(size_t)row * GG + col] = v;
            v.x = acc[im][in][2] + b0; v.y = acc[im][in][3] + b1;
            *(float2*)&g_xw[(size_t)(row + 8) * GG + col] = v;
        }
}

// ---------------------------------------------------------------------------
// fast two-level block reduction (512 threads = 16 warps)
// ---------------------------------------------------------------------------
__device__ __forceinline__ void block_reduce2(float& s, float& sq, float* shm) {
    int lane = threadIdx.x & 31;
    int wrp = threadIdx.x >> 5;
#pragma unroll
    for (int o = 16; o > 0; o >>= 1) {
        s  += __shfl_xor_sync(0xffffffffu, s, o);
        sq += __shfl_xor_sync(0xffffffffu, sq, o);
    }
    if (lane == 0) { shm[wrp] = s; shm[16 + wrp] = sq; }
    __syncthreads();
    if (wrp == 0) {
        float a = (lane < 16) ? shm[lane] : 0.f;
        float b = (lane < 16) ? shm[16 + lane] : 0.f;
#pragma unroll
        for (int o = 8; o > 0; o >>= 1) {
            a += __shfl_xor_sync(0xffffffffu, a, o);
            b += __shfl_xor_sync(0xffffffffu, b, o);
        }
        if (lane == 0) { shm[0] = a; shm[16] = b; }
    }
    __syncthreads();
    s = shm[0];
    sq = shm[16];
}

// ---------------------------------------------------------------------------
// Persistent recurrence: 128 blocks x 512 threads (16 warps = 4m x 4n).
// Block = (jn = blk & 63 -> N cols [32jn, 32jn+32), kc = blk >> 6 -> K half).
// Phase 1: partial GEMM, 2 passes:
//   pass A: h_hi x (W_hi, W_lo)   [needs only h_hi; h_lo streams via cp.async]
//   pass B: h_lo x W_hi
// W smem interleaved per 8-col group: rows g*16..g*16+7 = hi, +8..+15 = lo
// Phase 2 (blocks 0..63): LN + activations for batch row b = blk.
// ---------------------------------------------------------------------------
__global__ void __launch_bounds__(THR, 1) lstm_persist(
        const float* __restrict__ gg, const float* __restrict__ gb,
        const float* __restrict__ cgam, const float* __restrict__ cbet,
        float* __restrict__ out) {
    extern __shared__ unsigned char sm8[];
    __nv_bfloat16* Wm  = (__nv_bfloat16*)sm8;        // [64][WST] hi/lo interleaved
    __nv_bfloat16* Ahs = Wm + 64 * WST;              // [64][WST]
    __nv_bfloat16* Als = Ahs + 64 * WST;             // [64][WST]
    float* red = (float*)(Als + 64 * WST);           // [32]

    const int blk = blockIdx.x;
    const int tid = threadIdx.x;
    const int lane = tid & 31;
    const int wid = tid >> 5;
    const int wm = wid & 3, wn = wid >> 2;           // 4m x 4n
    const int lr = lane >> 2, lc = lane & 3;

    const int jn = blk & 63;
    const int kc = blk >> 6;                          // 0 or 1
    const int jb = jn * 32;                           // N-col base
    const int k0 = kc * 256;                          // K base within Wh
    const bool writer = (blk < WRT);

    // one-time: resident W tile, interleaved layout.
    {
        int c = tid >> 4;
        int seg = (tid & 15) * 16;
        int rh = (c >> 3) * 16 + (c & 7);
        const uint4* s = (const uint4*)&g_whi[(size_t)(jb + c) * KK + DD + k0 + seg];
        uint4* d = (uint4*)&Wm[rh * WST + seg];
        d[0] = s[0]; d[1] = s[1];
        s = (const uint4*)&g_wlo[(size_t)(jb + c) * KK + DD + k0 + seg];
        d = (uint4*)&Wm[(rh + 8) * WST + seg];
        d[0] = s[0]; d[1] = s[1];
    }

    // ldmatrix lane addressing
    const int a_g = lane >> 3;
    const int a_row_off = (a_g & 1) * 8 + (lane & 7);
    const int a_col_off = (a_g >> 1) * 8;
    // B x4 (merged hi/lo): matrices 0,1 = hi rows; 2,3 = lo rows
    const int b4_row = (lane & 7) + ((lane >> 4) & 1) * 8;
    const int b4_col = ((lane >> 3) & 1) * 8;
    // B x2 (hi only, pass B)
    const int b2_row = lane & 7;
    const int b2_col = ((lane >> 3) & 1) * 8;

    // phase-1 output coordinates
    const int p1_r = wm * 16 + lr;
    const int p1_c = jb + wn * 8 + lc * 2;

    // phase-2 constants (writers only; b = blk)
    const int b = blk;
    float gf = 0.f, bf = 0.f, gi = 0.f, bi = 0.f, gq = 0.f, bq = 0.f,
          go = 0.f, bo = 0.f, cga = 0.f, cbe = 0.f, creg = 0.f;
    if (writer) {
        gf = gg[tid];            bf = gb[tid];
        gi = gg[HH + tid];       bi = gb[HH + tid];
        gq = gg[2 * HH + tid];   bq = gb[2 * HH + tid];
        go = gg[3 * HH + tid];   bo = gb[3 * HH + tid];
        cga = cgam[tid];         cbe = cbet[tid];
        creg = g_c0[b * HH + tid];
    }
    float hlast = 0.f;

    // cp.async h-tile addressing (per thread: one 32-halfword (64B) row slice)
    const int h_r = tid >> 3;                 // 0..63
    const int h_seg = (tid & 7) * 32;         // halfword offset
    __nv_bfloat16* a_dst_h = &Ahs[h_r * WST + h_seg];
    __nv_bfloat16* a_dst_l = &Als[h_r * WST + h_seg];
    const __nv_bfloat16* a_src_h = &g_hhi[h_r * HH + k0 + h_seg];
    const __nv_bfloat16* a_src_l = &g_hlo[h_r * HH + k0 + h_seg];

    // xw prefetch (kc==0 blocks fold xw into their partial)
    float2 xwA = make_float2(0.f, 0.f), xwB = xwA;
    if (kc == 0) {
        xwA = __ldcg((const float2*)&g_xw[(size_t)p1_r * GG + p1_c]);
        xwB = __ldcg((const float2*)&g_xw[(size_t)(p1_r + 8) * GG + p1_c]);
    }

    const __nv_bfloat16* Abase_h = &Ahs[(wm * 16 + a_row_off) * WST + a_col_off];
    const __nv_bfloat16* Abase_l = &Als[(wm * 16 + a_row_off) * WST + a_col_off];
    const __nv_bfloat16* Bbase4 = &Wm[(wn * 16 + b4_row) * WST + b4_col];
    const __nv_bfloat16* Bbase2 = &Wm[(wn * 16 + b2_row) * WST + b2_col];

    for (int t = 0; t < TT; t++) {
        // ----- phase 1: issue h loads (hi group, then lo group) -----
        // each cp16 = 16 bytes = 8 halfwords; 4 per 32-halfword slice
        cp16(a_dst_h +  0, a_src_h +  0);
        cp16(a_dst_h +  8, a_src_h +  8);
        cp16(a_dst_h + 16, a_src_h + 16);
        cp16(a_dst_h + 24, a_src_h + 24);
        cp_commit();
        cp16(a_dst_l +  0, a_src_l +  0);
        cp16(a_dst_l +  8, a_src_l +  8);
        cp16(a_dst_l + 16, a_src_l + 16);
        cp16(a_dst_l + 24, a_src_l + 24);
        cp_commit();

        float acc[4] = {0.f, 0.f, 0.f, 0.f};

        // wait for hi group only, then pass A (2/3 of MMAs)
        asm volatile("cp.async.wait_group 1;");
        __syncthreads();
#pragma unroll 8
        for (int ks = 0; ks < 256; ks += 16) {
            unsigned ah[4], bm4[4];
            ldsm_x4(ah, Abase_h + ks);
            ldsm_x4(bm4, Bbase4 + ks);
            mma_bf16(acc, ah, bm4 + 0);      // h_hi x W_hi
            mma_bf16(acc, ah, bm4 + 2);      // h_hi x W_lo
        }

        // wait for lo group, then pass B
        asm volatile("cp.async.wait_group 0;");
        __syncthreads();
#pragma unroll 8
        for (int ks = 0; ks < 256; ks += 16) {
            unsigned al[4], bh[2];
            ldsm_x4(al, Abase_l + ks);
            ldsm_x2(bh, Bbase2 + ks);
            mma_bf16(acc, al, bh);           // h_lo x W_hi
        }

        // store partial (+ xw for kc==0)
        {
            float2 v;
            v.x = acc[0] + xwA.x; v.y = acc[1] + xwA.y;
            *(float2*)&g_part[((size_t)kc * BB + p1_r) * GG + p1_c] = v;
            v.x = acc[2] + xwB.x; v.y = acc[3] + xwB.y;
            *(float2*)&g_part[((size_t)kc * BB + p1_r + 8) * GG + p1_c] = v;
        }

        unsigned valA = 2u * t + 1u;
        unsigned valB = 2u * t + 2u;
        bar_arrive(blk, valA);

        if (writer) {
            bar_wait_all(valA);

            // ----- phase 2: batch row b, one gate element per thread -----
            const float* p0 = g_part + (size_t)b * GG;
            const float* p1 = g_part + (size_t)(BB + b) * GG;
            float vf = __ldcg(&p0[tid])          + __ldcg(&p1[tid]);
            float vi = __ldcg(&p0[HH + tid])     + __ldcg(&p1[HH + tid]);
            float vq = __ldcg(&p0[2 * HH + tid]) + __ldcg(&p1[2 * HH + tid]);
            float vo = __ldcg(&p0[3 * HH + tid]) + __ldcg(&p1[3 * HH + tid]);

            float s = vf + vi + vq + vo;
            float sq = vf * vf + vi * vi + vq * vq + vo * vo;
            block_reduce2(s, sq, red);
            float mean = s * (1.f / GG);
            float var = sq * (1.f / GG) - mean * mean;
            float rstd = rsqrtf(var + EPSV);

            float f = fast_sig((vf - mean) * rstd * gf + bf);
            float i = fast_sig((vi - mean) * rstd * gi + bi);
            float q = fast_tanh((vq - mean) * rstd * gq + bq);
            float o = fast_sig((vo - mean) * rstd * go + bo);
            float c = f * creg + i * q;

            float s2 = c, sq2 = c * c;
            block_reduce2(s2, sq2, red);
            float mean2 = s2 * (1.f / HH);
            float var2 = sq2 * (1.f / HH) - mean2 * mean2;
            float rstd2 = rsqrtf(var2 + EPSV);

            float cn = (c - mean2) * rstd2 * cga + cbe;
            float hn = o * fast_tanh(cn);
            creg = cn;
            hlast = hn;

            __nv_bfloat16 hi, lo;
            split2(hn, hi, lo);
            g_hhi[b * HH + tid] = hi;
            g_hlo[b * HH + tid] = lo;
            out[((size_t)t * BB + b) * HH + tid] = hn;

            bar_arrive(blk, valB);
        }

        // prefetch next step's xw while waiting (kc==0 only)
        if (kc == 0 && t + 1 < TT) {
            size_t tb = (size_t)(t + 1) * BB;
            xwA = __ldcg((const float2*)&g_xw[(tb + p1_r) * GG + p1_c]);
            xwB = __ldcg((const float2*)&g_xw[(tb + p1_r + 8) * GG + p1_c]);
        }

        bar_wait_writers(valB);
    }

    if (writer) {
        out[OUT_HC_OFF + b * HH + tid] = hlast;
        out[OUT_HC_OFF + BB * HH + b * HH + tid] = creg;
    }
}

// ---------------------------------------------------------------------------
extern "C" void kernel_launch(void* const* d_in, const int* in_sizes, int n_in,
                              void* d_out, int out_size) {
    const float* x    = (const float*)d_in[0];
    const float* h0   = (const float*)d_in[1];
    const float* c0   = (const float*)d_in[2];
    const float* w    = (const float*)d_in[3];
    const float* bias = (const float*)d_in[4];
    const float* gg   = (const float*)d_in[5];
    const float* gb   = (const float*)d_in[6];
    const float* cg   = (const float*)d_in[7];
    const float* cb   = (const float*)d_in[8];
    float* out = (float*)d_out;

    // smem: (64 W + 64 A-hi + 64 A-lo) rows * WST halfwords * 2B + red
    const int smem_bytes = 192 * WST * 2 + 256;

    static bool attr_set = false;
    if (!attr_set) {
        cudaFuncSetAttribute(lstm_persist,
                             cudaFuncAttributeMaxDynamicSharedMemorySize, smem_bytes);
        attr_set = true;
    }

    init_kernel<<<128, 256>>>(h0, c0);
    split_w_kernel<<<(KK * GG + 255) / 256, 256>>>(w);
    split_x_kernel<<<(int)(((size_t)MM * DD + 255) / 256), 256>>>(x);

    // XW = X @ Wx + bias : M=65536, N=2048, K=512
    gemm_x_kernel<<<dim3(GG / 128, MM / 128), 256>>>(bias);

    // persistent recurrence: all 1024 steps in one launch
    lstm_persist<<<NBLK, THR, smem_bytes>>>(gg, gb, cg, cb, out);
}

// round 10
// speedup vs baseline: 1.1793x; 1.1793x over previous
#include <cuda_runtime.h>
#include <cuda_bf16.h>
#include <math.h>

// Problem constants
#define TT 1024
#define BB 64
#define DD 512
#define HH 512
#define KK 1024            // D + H
#define GG 2048            // 4*H
#define EPSV 1e-5f
#define MM (TT * BB)       // 65536
#define OUT_HC_OFF (TT * BB * HH)
#define NBLK 128           // persistent blocks (<= 148 SMs)
#define WRT 64             // writer blocks (phase 2)
#define THR 512
#define WST 264            // smem halfword stride (conflict-free)

// Scratch (device globals — no runtime allocation allowed)
__device__ float g_xw[(size_t)MM * GG];                  // 512 MB
__device__ __nv_bfloat16 g_xhi[(size_t)MM * DD];
__device__ __nv_bfloat16 g_xlo[(size_t)MM * DD];
__device__ __nv_bfloat16 g_whi[(size_t)GG * KK];         // W^T [n][k]
__device__ __nv_bfloat16 g_wlo[(size_t)GG * KK];
__device__ __nv_bfloat16 g_hhi[BB * HH];
__device__ __nv_bfloat16 g_hlo[BB * HH];
__device__ float g_c0[BB * HH];
__device__ float g_part[2 * BB * GG];                     // 2 K-halves of gates
__device__ unsigned g_flags[NBLK * 8];                    // barrier flags, 32B apart

__device__ __forceinline__ void split2(float v, __nv_bfloat16& hi, __nv_bfloat16& lo) {
    hi = __float2bfloat16(v);
    lo = __float2bfloat16(v - __bfloat162float(hi));
}

__device__ __forceinline__ void mma_bf16(float* d, const unsigned* a, const unsigned* b) {
    asm volatile(
        "mma.sync.aligned.m16n8k16.row.col.f32.bf16.bf16.f32 "
        "{%0,%1,%2,%3}, {%4,%5,%6,%7}, {%8,%9}, {%0,%1,%2,%3};\n"
        : "+f"(d[0]), "+f"(d[1]), "+f"(d[2]), "+f"(d[3])
        : "r"(a[0]), "r"(a[1]), "r"(a[2]), "r"(a[3]), "r"(b[0]), "r"(b[1]));
}

__device__ __forceinline__ void ldsm_x4(unsigned* r, const void* p) {
    unsigned addr = (unsigned)__cvta_generic_to_shared(p);
    asm volatile("ldmatrix.sync.aligned.m8n8.x4.shared.b16 {%0,%1,%2,%3}, [%4];"
        : "=r"(r[0]), "=r"(r[1]), "=r"(r[2]), "=r"(r[3]) : "r"(addr));
}

__device__ __forceinline__ void st_release(unsigned* p, unsigned v) {
    asm volatile("st.release.gpu.u32 [%0], %1;" :: "l"(p), "r"(v) : "memory");
}
__device__ __forceinline__ unsigned ld_acquire(unsigned* p) {
    unsigned v;
    asm volatile("ld.acquire.gpu.u32 %0, [%1];" : "=r"(v) : "l"(p) : "memory");
    return v;
}

// flag barrier pieces (R7-verified protocol)
__device__ __forceinline__ void bar_arrive(int blk, unsigned val) {
    __syncthreads();
    if (threadIdx.x == 0) st_release(&g_flags[blk * 8], val);
}
__device__ __forceinline__ void bar_wait_all(unsigned val) {
    if (threadIdx.x < NBLK) {
        while (ld_acquire(&g_flags[threadIdx.x * 8]) < val) { }
    }
    __syncthreads();
}
__device__ __forceinline__ void bar_wait_writers(unsigned val) {
    if (threadIdx.x < WRT) {
        while (ld_acquire(&g_flags[threadIdx.x * 8]) < val) { }
    }
    __syncthreads();
}

__device__ __forceinline__ float fast_sig(float x) {
    return __fdividef(1.f, 1.f + __expf(-x));
}
__device__ __forceinline__ float fast_tanh(float x) {
    return __fdividef(2.f, 1.f + __expf(-2.f * x)) - 1.f;
}

// ---------------------------------------------------------------------------
__global__ void init_kernel(const float* __restrict__ h0,
                            const float* __restrict__ c0) {
    int i = blockIdx.x * blockDim.x + threadIdx.x;
    if (i < NBLK * 8) g_flags[i] = 0;
    if (i < BB * HH) {
        split2(h0[i], g_hhi[i], g_hlo[i]);
        g_c0[i] = c0[i];
    }
}

__global__ void split_w_kernel(const float* __restrict__ w) {
    int idx = blockIdx.x * blockDim.x + threadIdx.x;
    if (idx < KK * GG) {
        int k = idx / GG;
        int n = idx % GG;
        __nv_bfloat16 hi, lo;
        split2(w[idx], hi, lo);
        g_whi[(size_t)n * KK + k] = hi;
        g_wlo[(size_t)n * KK + k] = lo;
    }
}

__global__ void split_x_kernel(const float* __restrict__ x) {
    size_t idx = (size_t)blockIdx.x * blockDim.x + threadIdx.x;
    if (idx < (size_t)MM * DD) {
        split2(x[idx], g_xhi[idx], g_xlo[idx]);
    }
}

// ---------------------------------------------------------------------------
// XW = X @ Wx + bias via bf16-split HMMA.  M=65536, N=2048, K=512.
// Staging identical to verified version; fragment loads now via ldmatrix
// (A x4 geometry verified in persist R7; B x4 pair-merge geometry verified R9).
// ---------------------------------------------------------------------------
__global__ void __launch_bounds__(256, 1) gemm_x_kernel(const float* __restrict__ bias) {
    __shared__ __nv_bfloat16 Ah[128][40], Al[128][40], Bh[128][40], Bl[128][40];

    const int bn = blockIdx.x * 128;
    const int bm = blockIdx.y * 128;
    const int tid = threadIdx.x;
    const int wid = tid >> 5, lane = tid & 31;
    const int wm = wid & 1, wn = wid >> 1;
    const int lr = lane >> 2, lc = lane & 3;

    // ldmatrix lane addressing
    const int a_g = lane >> 3;
    const int a_row_off = (a_g & 1) * 8 + (lane & 7);
    const int a_col_off = (a_g >> 1) * 8;
    const int b4_row = (lane & 7) + ((lane >> 4) & 1) * 8;
    const int b4_col = ((lane >> 3) & 1) * 8;

    float acc[4][4][4];
#pragma unroll
    for (int i = 0; i < 4; i++)
#pragma unroll
        for (int j = 0; j < 4; j++)
#pragma unroll
            for (int q = 0; q < 4; q++) acc[i][j][q] = 0.f;

    const int ldr = tid >> 1;
    const int ldc = (tid & 1) * 16;

    for (int k0 = 0; k0 < DD; k0 += 32) {
        const uint4* s;
        s = (const uint4*)&g_xhi[(size_t)(bm + ldr) * DD + k0 + ldc];
        *(uint4*)&Ah[ldr][ldc] = s[0];  *(uint4*)&Ah[ldr][ldc + 8] = s[1];
        s = (const uint4*)&g_xlo[(size_t)(bm + ldr) * DD + k0 + ldc];
        *(uint4*)&Al[ldr][ldc] = s[0];  *(uint4*)&Al[ldr][ldc + 8] = s[1];
        s = (const uint4*)&g_whi[(size_t)(bn + ldr) * KK + k0 + ldc];
        *(uint4*)&Bh[ldr][ldc] = s[0];  *(uint4*)&Bh[ldr][ldc + 8] = s[1];
        s = (const uint4*)&g_wlo[(size_t)(bn + ldr) * KK + k0 + ldc];
        *(uint4*)&Bl[ldr][ldc] = s[0];  *(uint4*)&Bl[ldr][ldc + 8] = s[1];
        __syncthreads();

#pragma unroll
        for (int ks = 0; ks < 32; ks += 16) {
            unsigned ahi[4][4], alo[4][4], bhi[2][4], blo[2][4];
#pragma unroll
            for (int im = 0; im < 4; im++) {
                ldsm_x4(ahi[im], &Ah[wm * 64 + im * 16 + a_row_off][ks + a_col_off]);
                ldsm_x4(alo[im], &Al[wm * 64 + im * 16 + a_row_off][ks + a_col_off]);
            }
#pragma unroll
            for (int inp = 0; inp < 2; inp++) {
                ldsm_x4(bhi[inp], &Bh[wn * 32 + inp * 16 + b4_row][ks + b4_col]);
                ldsm_x4(blo[inp], &Bl[wn * 32 + inp * 16 + b4_row][ks + b4_col]);
            }
#pragma unroll
            for (int im = 0; im < 4; im++)
#pragma unroll
                for (int in = 0; in < 4; in++) {
                    const unsigned* bh = bhi[in >> 1] + (in & 1) * 2;
                    const unsigned* bl = blo[in >> 1] + (in & 1) * 2;
                    mma_bf16(acc[im][in], ahi[im], bh);
                    mma_bf16(acc[im][in], alo[im], bh);
                    mma_bf16(acc[im][in], ahi[im], bl);
                }
        }
        __syncthreads();
    }

#pragma unroll
    for (int im = 0; im < 4; im++)
#pragma unroll
        for (int in = 0; in < 4; in++) {
            int row = bm + wm * 64 + im * 16 + lr;
            int col = bn + wn * 32 + in * 8 + lc * 2;
            float b0 = bias[col], b1 = bias[col + 1];
            float2 v;
            v.x = acc[im][in][0] + b0; v.y = acc[im][in][1] + b1;
            *(float2*)&g_xw[(size_t)row * GG + col] = v;
            v.x = acc[im][in][2] + b0; v.y = acc[im][in][3] + b1;
            *(float2*)&g_xw[(size_t)(row + 8) * GG + col] = v;
        }
}

// ---------------------------------------------------------------------------
// fast two-level block reduction (512 threads = 16 warps) — verified R9
// ---------------------------------------------------------------------------
__device__ __forceinline__ void block_reduce2(float& s, float& sq, float* shm) {
    int lane = threadIdx.x & 31;
    int wrp = threadIdx.x >> 5;
#pragma unroll
    for (int o = 16; o > 0; o >>= 1) {
        s  += __shfl_xor_sync(0xffffffffu, s, o);
        sq += __shfl_xor_sync(0xffffffffu, sq, o);
    }
    if (lane == 0) { shm[wrp] = s; shm[16 + wrp] = sq; }
    __syncthreads();
    if (wrp == 0) {
        float a = (lane < 16) ? shm[lane] : 0.f;
        float b = (lane < 16) ? shm[16 + lane] : 0.f;
#pragma unroll
        for (int o = 8; o > 0; o >>= 1) {
            a += __shfl_xor_sync(0xffffffffu, a, o);
            b += __shfl_xor_sync(0xffffffffu, b, o);
        }
        if (lane == 0) { shm[0] = a; shm[16] = b; }
    }
    __syncthreads();
    s = shm[0];
    sq = shm[16];
}

// ---------------------------------------------------------------------------
// Persistent recurrence: 128 blocks x 512 threads (16 warps = 4m x 4n).
// R7 single-pass flow + R9 merged-W interleaved layout (both HW-verified).
// Phase 1: 3 ldsm_x4 + 3 MMA per k16.  Phase 2 (blocks 0..63): LN + act.
// ---------------------------------------------------------------------------
__global__ void __launch_bounds__(THR, 1) lstm_persist(
        const float* __restrict__ gg, const float* __restrict__ gb,
        const float* __restrict__ cgam, const float* __restrict__ cbet,
        float* __restrict__ out) {
    extern __shared__ unsigned char sm8[];
    __nv_bfloat16* Wm  = (__nv_bfloat16*)sm8;        // [64][WST] hi/lo interleaved
    __nv_bfloat16* Ahs = Wm + 64 * WST;              // [64][WST]
    __nv_bfloat16* Als = Ahs + 64 * WST;             // [64][WST]
    float* red = (float*)(Als + 64 * WST);           // [32]

    const int blk = blockIdx.x;
    const int tid = threadIdx.x;
    const int lane = tid & 31;
    const int wid = tid >> 5;
    const int wm = wid & 3, wn = wid >> 2;           // 4m x 4n
    const int lr = lane >> 2, lc = lane & 3;

    const int jn = blk & 63;
    const int kc = blk >> 6;                          // 0 or 1
    const int jb = jn * 32;                           // N-col base
    const int k0 = kc * 256;                          // K base within Wh
    const bool writer = (blk < WRT);

    // one-time: resident W tile, interleaved (verified R9):
    // col c -> row (c>>3)*16 + (c&7) = hi, +8 = lo
    {
        int c = tid >> 4;
        int seg = (tid & 15) * 16;
        int rh = (c >> 3) * 16 + (c & 7);
        const uint4* s = (const uint4*)&g_whi[(size_t)(jb + c) * KK + DD + k0 + seg];
        uint4* d = (uint4*)&Wm[rh * WST + seg];
        d[0] = s[0]; d[1] = s[1];
        s = (const uint4*)&g_wlo[(size_t)(jb + c) * KK + DD + k0 + seg];
        d = (uint4*)&Wm[(rh + 8) * WST + seg];
        d[0] = s[0]; d[1] = s[1];
    }

    // ldmatrix lane addressing (verified)
    const int a_g = lane >> 3;
    const int a_row_off = (a_g & 1) * 8 + (lane & 7);
    const int a_col_off = (a_g >> 1) * 8;
    const int b4_row = (lane & 7) + ((lane >> 4) & 1) * 8;
    const int b4_col = ((lane >> 3) & 1) * 8;

    // phase-1 output coordinates
    const int p1_r = wm * 16 + lr;
    const int p1_c = jb + wn * 8 + lc * 2;

    // phase-2 constants (writers only; b = blk)
    const int b = blk;
    float gf = 0.f, bf = 0.f, gi = 0.f, bi = 0.f, gq = 0.f, bq = 0.f,
          go = 0.f, bo = 0.f, cga = 0.f, cbe = 0.f, creg = 0.f;
    if (writer) {
        gf = gg[tid];            bf = gb[tid];
        gi = gg[HH + tid];       bi = gb[HH + tid];
        gq = gg[2 * HH + tid];   bq = gb[2 * HH + tid];
        go = gg[3 * HH + tid];   bo = gb[3 * HH + tid];
        cga = cgam[tid];         cbe = cbet[tid];
        creg = g_c0[b * HH + tid];
    }
    float hlast = 0.f;

    // xw prefetch (kc==0 blocks fold xw into their partial)
    float2 xwA = make_float2(0.f, 0.f), xwB = xwA;
    if (kc == 0) {
        xwA = __ldcg((const float2*)&g_xw[(size_t)p1_r * GG + p1_c]);
        xwB = __ldcg((const float2*)&g_xw[(size_t)(p1_r + 8) * GG + p1_c]);
    }

    const __nv_bfloat16* Abase_h = &Ahs[(wm * 16 + a_row_off) * WST + a_col_off];
    const __nv_bfloat16* Abase_l = &Als[(wm * 16 + a_row_off) * WST + a_col_off];
    const __nv_bfloat16* Bbase4 = &Wm[(wn * 16 + b4_row) * WST + b4_col];

    for (int t = 0; t < TT; t++) {
        // ----- phase 1: load h tile (64 x 256 hi/lo) — R7-verified fill -----
        // 8 threads/row x 32 halfwords (4 uint4) each
        {
            int r = tid >> 3;                 // 0..63
            int seg = (tid & 7) * 32;
            const uint4* s = (const uint4*)&g_hhi[r * HH + k0 + seg];
            uint4* d = (uint4*)&Ahs[r * WST + seg];
            d[0] = __ldcg(s + 0); d[1] = __ldcg(s + 1);
            d[2] = __ldcg(s + 2); d[3] = __ldcg(s + 3);
            s = (const uint4*)&g_hlo[r * HH + k0 + seg];
            d = (uint4*)&Als[r * WST + seg];
            d[0] = __ldcg(s + 0); d[1] = __ldcg(s + 1);
            d[2] = __ldcg(s + 2); d[3] = __ldcg(s + 3);
        }
        __syncthreads();

        float acc[4] = {0.f, 0.f, 0.f, 0.f};

#pragma unroll 8
        for (int ks = 0; ks < 256; ks += 16) {
            unsigned ah[4], al[4], bm4[4];
            ldsm_x4(ah, Abase_h + ks);
            ldsm_x4(al, Abase_l + ks);
            ldsm_x4(bm4, Bbase4 + ks);
            mma_bf16(acc, ah, bm4 + 0);      // h_hi x W_hi
            mma_bf16(acc, al, bm4 + 0);      // h_lo x W_hi
            mma_bf16(acc, ah, bm4 + 2);      // h_hi x W_lo
        }

        // store partial (+ xw for kc==0)
        {
            float2 v;
            v.x = acc[0] + xwA.x; v.y = acc[1] + xwA.y;
            *(float2*)&g_part[((size_t)kc * BB + p1_r) * GG + p1_c] = v;
            v.x = acc[2] + xwB.x; v.y = acc[3] + xwB.y;
            *(float2*)&g_part[((size_t)kc * BB + p1_r + 8) * GG + p1_c] = v;
        }

        unsigned valA = 2u * t + 1u;
        unsigned valB = 2u * t + 2u;
        bar_arrive(blk, valA);

        float hn = 0.f;
        if (writer) {
            bar_wait_all(valA);

            // ----- phase 2: batch row b, one gate element per thread -----
            const float* p0 = g_part + (size_t)b * GG;
            const float* p1 = g_part + (size_t)(BB + b) * GG;
            float vf = __ldcg(&p0[tid])          + __ldcg(&p1[tid]);
            float vi = __ldcg(&p0[HH + tid])     + __ldcg(&p1[HH + tid]);
            float vq = __ldcg(&p0[2 * HH + tid]) + __ldcg(&p1[2 * HH + tid]);
            float vo = __ldcg(&p0[3 * HH + tid]) + __ldcg(&p1[3 * HH + tid]);

            float s = vf + vi + vq + vo;
            float sq = vf * vf + vi * vi + vq * vq + vo * vo;
            block_reduce2(s, sq, red);
            float mean = s * (1.f / GG);
            float var = sq * (1.f / GG) - mean * mean;
            float rstd = rsqrtf(var + EPSV);

            float f = fast_sig((vf - mean) * rstd * gf + bf);
            float i = fast_sig((vi - mean) * rstd * gi + bi);
            float q = fast_tanh((vq - mean) * rstd * gq + bq);
            float o = fast_sig((vo - mean) * rstd * go + bo);
            float c = f * creg + i * q;

            float s2 = c, sq2 = c * c;
            block_reduce2(s2, sq2, red);
            float mean2 = s2 * (1.f / HH);
            float var2 = sq2 * (1.f / HH) - mean2 * mean2;
            float rstd2 = rsqrtf(var2 + EPSV);

            float cn = (c - mean2) * rstd2 * cga + cbe;
            hn = o * fast_tanh(cn);
            creg = cn;
            hlast = hn;

            __nv_bfloat16 hi, lo;
            split2(hn, hi, lo);
            g_hhi[b * HH + tid] = hi;
            g_hlo[b * HH + tid] = lo;

            bar_arrive(blk, valB);     // releases g_hhi/g_hlo (st.release orders)

            // out store not needed by other blocks — after the release
            out[((size_t)t * BB + b) * HH + tid] = hn;
        }

        // prefetch next step's xw while waiting (kc==0 only)
        if (kc == 0 && t + 1 < TT) {
            size_t tb = (size_t)(t + 1) * BB;
            xwA = __ldcg((const float2*)&g_xw[(tb + p1_r) * GG + p1_c]);
            xwB = __ldcg((const float2*)&g_xw[(tb + p1_r + 8) * GG + p1_c]);
        }

        bar_wait_writers(valB);
    }

    if (writer) {
        out[OUT_HC_OFF + b * HH + tid] = hlast;
        out[OUT_HC_OFF + BB * HH + b * HH + tid] = creg;
    }
}

// ---------------------------------------------------------------------------
extern "C" void kernel_launch(void* const* d_in, const int* in_sizes, int n_in,
                              void* d_out, int out_size) {
    const float* x    = (const float*)d_in[0];
    const float* h0   = (const float*)d_in[1];
    const float* c0   = (const float*)d_in[2];
    const float* w    = (const float*)d_in[3];
    const float* bias = (const float*)d_in[4];
    const float* gg   = (const float*)d_in[5];
    const float* gb   = (const float*)d_in[6];
    const float* cg   = (const float*)d_in[7];
    const float* cb   = (const float*)d_in[8];
    float* out = (float*)d_out;

    // smem: (64 W + 64 A-hi + 64 A-lo) rows * WST halfwords * 2B + red
    const int smem_bytes = 192 * WST * 2 + 256;

    static bool attr_set = false;
    if (!attr_set) {
        cudaFuncSetAttribute(lstm_persist,
                             cudaFuncAttributeMaxDynamicSharedMemorySize, smem_bytes);
        attr_set = true;
    }

    init_kernel<<<128, 256>>>(h0, c0);
    split_w_kernel<<<(KK * GG + 255) / 256, 256>>>(w);
    split_x_kernel<<<(int)(((size_t)MM * DD + 255) / 256), 256>>>(x);

    // XW = X @ Wx + bias : M=65536, N=2048, K=512
    gemm_x_kernel<<<dim3(GG / 128, MM / 128), 256>>>(bias);

    // persistent recurrence: all 1024 steps in one launch
    lstm_persist<<<NBLK, THR, smem_bytes>>>(gg, gb, cg, cb, out);
}